// round 3
// baseline (speedup 1.0000x reference)
#include <cuda_runtime.h>

// Problem constants (fixed by the dataset instance)
#define BB    2
#define TT    2048
#define DD    1024
#define HH    16
#define HDIM  64
#define NQKV  (3*DD)          // 3072
#define MROWS (BB*TT)         // 4096

// Scratch (allocation-free rule: __device__ globals)
__device__ float g_qkv[(size_t)MROWS * NQKV];   // [B*T, 3D]
__device__ float g_attn[(size_t)MROWS * DD];    // [B*T, D]  (attn output, head-concat layout)

// ---------------------------------------------------------------------------
// C[M,N] = A[M,K] @ B[N,K]^T + bias[N]        (torch Linear: y = x W^T + b)
// 128x128x16 tiles, 256 threads, 8x8 per-thread fragment.
// ---------------------------------------------------------------------------
__global__ void __launch_bounds__(256, 2)
sgemm_nt_bias(const float* __restrict__ A, const float* __restrict__ B,
              const float* __restrict__ bias, float* __restrict__ C,
              int M, int N, int K)
{
    __shared__ float As[16][132];   // [k][m], +4 pad
    __shared__ float Bs[16][132];   // [k][n], +4 pad

    const int tid = threadIdx.x;
    const int tx  = tid & 15;
    const int ty  = tid >> 4;
    const int m0  = blockIdx.y * 128;
    const int n0  = blockIdx.x * 128;

    float acc[8][8];
    #pragma unroll
    for (int i = 0; i < 8; i++)
        #pragma unroll
        for (int j = 0; j < 8; j++) acc[i][j] = 0.f;

    for (int k0 = 0; k0 < K; k0 += 16) {
        // Load 128 rows x 16 k of A and B (512 float4 each; 2 per thread)
        #pragma unroll
        for (int it = 0; it < 2; it++) {
            int f   = tid + it * 256;
            int row = f >> 2;
            int k4  = f & 3;
            float4 va = *(const float4*)(A + (size_t)(m0 + row) * K + k0 + k4 * 4);
            As[k4*4+0][row] = va.x; As[k4*4+1][row] = va.y;
            As[k4*4+2][row] = va.z; As[k4*4+3][row] = va.w;
            float4 vb = *(const float4*)(B + (size_t)(n0 + row) * K + k0 + k4 * 4);
            Bs[k4*4+0][row] = vb.x; Bs[k4*4+1][row] = vb.y;
            Bs[k4*4+2][row] = vb.z; Bs[k4*4+3][row] = vb.w;
        }
        __syncthreads();

        #pragma unroll
        for (int kk = 0; kk < 16; kk++) {
            float a[8], b[8];
            *(float4*)&a[0] = *(const float4*)&As[kk][ty*8];
            *(float4*)&a[4] = *(const float4*)&As[kk][ty*8+4];
            *(float4*)&b[0] = *(const float4*)&Bs[kk][tx*8];
            *(float4*)&b[4] = *(const float4*)&Bs[kk][tx*8+4];
            #pragma unroll
            for (int i = 0; i < 8; i++)
                #pragma unroll
                for (int j = 0; j < 8; j++)
                    acc[i][j] += a[i] * b[j];
        }
        __syncthreads();
    }

    float bv[8];
    #pragma unroll
    for (int j = 0; j < 8; j++) bv[j] = bias[n0 + tx*8 + j];

    #pragma unroll
    for (int i = 0; i < 8; i++) {
        float* cp = C + (size_t)(m0 + ty*8 + i) * N + n0 + tx*8;
        *(float4*)(cp + 0) = make_float4(acc[i][0]+bv[0], acc[i][1]+bv[1],
                                         acc[i][2]+bv[2], acc[i][3]+bv[3]);
        *(float4*)(cp + 4) = make_float4(acc[i][4]+bv[4], acc[i][5]+bv[5],
                                         acc[i][6]+bv[6], acc[i][7]+bv[7]);
    }
}

// ---------------------------------------------------------------------------
// Flash attention, causal, fp32. One CTA per (64-row q-tile, head, batch).
// Reference head layout: head h uses qkv columns [h*192 .. h*192+191] as
// q(64) | k(64) | v(64). Output written in [B,T,H*hd] concat layout.
// ---------------------------------------------------------------------------
#define FA_STRIDE 65   // 64 + 1 pad (scalar smem access; avoids bank pathologies)

__global__ void __launch_bounds__(256)
flash_attn(const float* __restrict__ qkv, float* __restrict__ out)
{
    extern __shared__ float sm[];
    float* Qs = sm;                       // [64][65]
    float* Ks = sm + 1 * 64 * FA_STRIDE;  // [64][65]
    float* Vs = sm + 2 * 64 * FA_STRIDE;  // [64][65]
    float* Ps = sm + 3 * 64 * FA_STRIDE;  // [64][65]

    const int iq  = blockIdx.x;   // q tile index (0..31)
    const int h   = blockIdx.y;
    const int b   = blockIdx.z;
    const int tid = threadIdx.x;
    const int tx  = tid & 15;     // col group (S cols / hd cols)
    const int ty  = tid >> 4;     // row group (q rows)

    const float* base = qkv + (size_t)b * TT * NQKV + h * (3 * HDIM);

    // Load Q tile [64 tokens][64 dims]
    #pragma unroll
    for (int it = 0; it < 4; it++) {
        int f  = tid + it * 256;
        int s  = f >> 4;
        int c4 = f & 15;
        float4 v = *(const float4*)(base + (size_t)(iq*64 + s) * NQKV + c4 * 4);
        float* q = Qs + s * FA_STRIDE + c4 * 4;
        q[0] = v.x; q[1] = v.y; q[2] = v.z; q[3] = v.w;
    }

    float m[4], l[4], o[4][4];
    #pragma unroll
    for (int r = 0; r < 4; r++) {
        m[r] = -1e30f; l[r] = 0.f;
        #pragma unroll
        for (int c = 0; c < 4; c++) o[r][c] = 0.f;
    }

    for (int j = 0; j <= iq; j++) {
        __syncthreads();   // previous iteration's readers of Ks/Vs/Ps done
        // Load K and V tiles for key block j
        #pragma unroll
        for (int it = 0; it < 4; it++) {
            int f  = tid + it * 256;
            int s  = f >> 4;
            int c4 = f & 15;
            const float* kp = base + (size_t)(j*64 + s) * NQKV + HDIM + c4 * 4;
            float4 kv = *(const float4*)kp;
            float4 vv = *(const float4*)(kp + HDIM);
            float* kd = Ks + s * FA_STRIDE + c4 * 4;
            kd[0] = kv.x; kd[1] = kv.y; kd[2] = kv.z; kd[3] = kv.w;
            float* vd = Vs + s * FA_STRIDE + c4 * 4;
            vd[0] = vv.x; vd[1] = vv.y; vd[2] = vv.z; vd[3] = vv.w;
        }
        __syncthreads();

        // S = Q @ K^T (per-thread 4x4 fragment)
        float sacc[4][4];
        #pragma unroll
        for (int r = 0; r < 4; r++)
            #pragma unroll
            for (int c = 0; c < 4; c++) sacc[r][c] = 0.f;

        #pragma unroll 8
        for (int k = 0; k < 64; k++) {
            float qv[4], kv[4];
            #pragma unroll
            for (int r = 0; r < 4; r++) qv[r] = Qs[(ty*4 + r) * FA_STRIDE + k];
            #pragma unroll
            for (int c = 0; c < 4; c++) kv[c] = Ks[(tx*4 + c) * FA_STRIDE + k];
            #pragma unroll
            for (int r = 0; r < 4; r++)
                #pragma unroll
                for (int c = 0; c < 4; c++) sacc[r][c] += qv[r] * kv[c];
        }

        const bool diag = (j == iq);
        #pragma unroll
        for (int r = 0; r < 4; r++)
            #pragma unroll
            for (int c = 0; c < 4; c++) {
                float v = sacc[r][c] * 0.125f;   // 1/sqrt(64)
                if (diag && (tx*4 + c) > (ty*4 + r)) v = -1e30f;
                sacc[r][c] = v;
            }

        // Online softmax update (row group = 16 lanes sharing ty; shfl width 16)
        #pragma unroll
        for (int r = 0; r < 4; r++) {
            float rmax = fmaxf(fmaxf(sacc[r][0], sacc[r][1]),
                               fmaxf(sacc[r][2], sacc[r][3]));
            #pragma unroll
            for (int off = 8; off > 0; off >>= 1)
                rmax = fmaxf(rmax, __shfl_xor_sync(0xffffffffu, rmax, off));

            float mn   = fmaxf(m[r], rmax);
            float corr = __expf(m[r] - mn);

            float rs = 0.f;
            #pragma unroll
            for (int c = 0; c < 4; c++) {
                float p = __expf(sacc[r][c] - mn);
                sacc[r][c] = p;
                rs += p;
            }
            #pragma unroll
            for (int off = 8; off > 0; off >>= 1)
                rs += __shfl_xor_sync(0xffffffffu, rs, off);

            l[r] = l[r] * corr + rs;
            #pragma unroll
            for (int c = 0; c < 4; c++) o[r][c] *= corr;
            m[r] = mn;

            float* pd = Ps + (ty*4 + r) * FA_STRIDE + tx*4;
            pd[0] = sacc[r][0]; pd[1] = sacc[r][1];
            pd[2] = sacc[r][2]; pd[3] = sacc[r][3];
        }
        __syncthreads();

        // O += P @ V
        #pragma unroll 8
        for (int s = 0; s < 64; s++) {
            float pv[4], vv[4];
            #pragma unroll
            for (int r = 0; r < 4; r++) pv[r] = Ps[(ty*4 + r) * FA_STRIDE + s];
            #pragma unroll
            for (int c = 0; c < 4; c++) vv[c] = Vs[s * FA_STRIDE + tx*4 + c];
            #pragma unroll
            for (int r = 0; r < 4; r++)
                #pragma unroll
                for (int c = 0; c < 4; c++) o[r][c] += pv[r] * vv[c];
        }
    }

    // Epilogue: normalize and write [B,T,H*hd]
    #pragma unroll
    for (int r = 0; r < 4; r++) {
        float inv = 1.f / l[r];
        float* op = out + ((size_t)b * TT + iq*64 + ty*4 + r) * DD + h * HDIM + tx*4;
        *(float4*)op = make_float4(o[r][0]*inv, o[r][1]*inv, o[r][2]*inv, o[r][3]*inv);
    }
}

// ---------------------------------------------------------------------------
// Launch: qkv GEMM -> flash attention -> output GEMM (same stream, in order).
// ---------------------------------------------------------------------------
extern "C" void kernel_launch(void* const* d_in, const int* in_sizes, int n_in,
                              void* d_out, int out_size)
{
    const float* x     = (const float*)d_in[0];   // [B,T,D]
    const float* Wqkv  = (const float*)d_in[1];   // [3D,D]
    const float* bqkv  = (const float*)d_in[2];   // [3D]
    const float* Wout  = (const float*)d_in[3];   // [D,D]
    const float* bout  = (const float*)d_in[4];   // [D]
    float*       out   = (float*)d_out;           // [B,T,D]

    float* qkvbuf  = nullptr;
    float* attnbuf = nullptr;
    cudaGetSymbolAddress((void**)&qkvbuf,  g_qkv);
    cudaGetSymbolAddress((void**)&attnbuf, g_attn);

    const int fa_smem = 4 * 64 * FA_STRIDE * (int)sizeof(float);   // 66560 B
    cudaFuncSetAttribute(flash_attn, cudaFuncAttributeMaxDynamicSharedMemorySize, fa_smem);

    // 1) qkv = x @ Wqkv^T + bqkv   [4096, 3072]
    {
        dim3 grid(NQKV / 128, MROWS / 128);   // (24, 32)
        sgemm_nt_bias<<<grid, 256>>>(x, Wqkv, bqkv, qkvbuf, MROWS, NQKV, DD);
    }
    // 2) attention
    {
        dim3 grid(TT / 64, HH, BB);           // (32, 16, 2)
        flash_attn<<<grid, 256, fa_smem>>>(qkvbuf, attnbuf);
    }
    // 3) out = attn @ Wout^T + bout  [4096, 1024]
    {
        dim3 grid(DD / 128, MROWS / 128);     // (8, 32)
        sgemm_nt_bias<<<grid, 256>>>(attnbuf, Wout, bout, out, MROWS, DD, DD);
    }
}

// round 8
// speedup vs baseline: 1.3889x; 1.3889x over previous
#include <cuda_runtime.h>
#include <cstdint>

// Problem constants (fixed by the dataset instance)
#define BB    2
#define TT    2048
#define DD    1024
#define HH    16
#define HDIM  64
#define NQKV  (3*DD)          // 3072
#define MROWS (BB*TT)         // 4096

// Scratch (allocation-free rule: __device__ globals)
__device__ float g_qkv[(size_t)MROWS * NQKV];   // [B*T, 3D]
__device__ float g_attn[(size_t)MROWS * DD];    // [B*T, D]

// ===========================================================================
// Baseline-PTX helpers (NO sm_103a-gated instructions — harness compiles a
// compute_103 PTX stage where tcgen05/.kind::tf32 etc. are illegal).
// ===========================================================================
__device__ __forceinline__ uint32_t smem_u32(const void* p) {
    uint32_t a;
    asm("{ .reg .u64 t; cvta.to.shared.u64 t, %1; cvt.u32.u64 %0, t; }"
        : "=r"(a) : "l"(p));
    return a;
}

__device__ __forceinline__ void ldm_x4(uint32_t r[4], uint32_t addr) {
    asm volatile("ldmatrix.sync.aligned.m8n8.x4.shared.b16 {%0,%1,%2,%3}, [%4];"
                 : "=r"(r[0]), "=r"(r[1]), "=r"(r[2]), "=r"(r[3]) : "r"(addr));
}

__device__ __forceinline__ void mma_bf16(float c[4], const uint32_t a[4],
                                         uint32_t b0, uint32_t b1) {
    asm volatile(
        "mma.sync.aligned.m16n8k16.row.col.f32.bf16.bf16.f32 "
        "{%0,%1,%2,%3}, {%4,%5,%6,%7}, {%8,%9}, {%0,%1,%2,%3};"
        : "+f"(c[0]), "+f"(c[1]), "+f"(c[2]), "+f"(c[3])
        : "r"(a[0]), "r"(a[1]), "r"(a[2]), "r"(a[3]), "r"(b0), "r"(b1));
}

// pack two floats (lo = smaller-k element) into bf16x2 (lo -> lower 16 bits)
__device__ __forceinline__ uint32_t packbf(float lo, float hi) {
    uint32_t r;
    asm("cvt.rn.bf16x2.f32 %0, %1, %2;" : "=r"(r) : "f"(hi), "f"(lo));
    return r;
}

// split float4 (4 consecutive k) into hi-pair / lo-pair bf16x2 words
__device__ __forceinline__ void split4(float4 v, uint2& h, uint2& l) {
    uint32_t h0 = packbf(v.x, v.y);
    uint32_t h1 = packbf(v.z, v.w);
    float hx = __uint_as_float(h0 << 16);
    float hy = __uint_as_float(h0 & 0xffff0000u);
    float hz = __uint_as_float(h1 << 16);
    float hw = __uint_as_float(h1 & 0xffff0000u);
    h.x = h0; h.y = h1;
    l.x = packbf(v.x - hx, v.y - hy);
    l.y = packbf(v.z - hz, v.w - hw);
}

__device__ __forceinline__ void sts64(uint32_t addr, uint2 v) {
    asm volatile("st.shared.v2.b32 [%0], {%1,%2};"
                 :: "r"(addr), "r"(v.x), "r"(v.y) : "memory");
}

// ===========================================================================
// 3x-BF16 tensor-core GEMM: C[M,N] = A[M,K] @ B[N,K]^T + bias[N]
// CTA 128x128, 8 warps (warp tile 64x32), K-step 32, fp32 accumulate.
// smem: Ah,Al,Bh,Bl bf16 tiles [128 rows][80B row stride] (ldmatrix-friendly:
// row offsets mod 128B = {0,80,32,112,64,16,96,48} -> conflict-free x4 loads).
// ===========================================================================
#define RS 80
#define TILE_B (128 * RS)        // 10240 B per tile
#define GK_SMEM (4 * TILE_B + 128)

__global__ void __launch_bounds__(256)
bf16x3_gemm_nt_bias(const float* __restrict__ A, const float* __restrict__ B,
                    const float* __restrict__ bias, float* __restrict__ C,
                    int M, int N, int K)
{
    extern __shared__ char smem[];
    const uint32_t sb  = (smem_u32(smem) + 127) & ~127u;
    const uint32_t sAh = sb;
    const uint32_t sAl = sb + TILE_B;
    const uint32_t sBh = sb + 2 * TILE_B;
    const uint32_t sBl = sb + 3 * TILE_B;

    const int tid  = threadIdx.x;
    const int lane = tid & 31;
    const int wid  = tid >> 5;
    const int wm   = wid & 1;
    const int wn   = wid >> 1;
    const int m0   = blockIdx.y * 128;
    const int n0   = blockIdx.x * 128;

    float acc[4][4][4];
    #pragma unroll
    for (int i = 0; i < 4; i++)
        #pragma unroll
        for (int j = 0; j < 4; j++)
            #pragma unroll
            for (int q = 0; q < 4; q++) acc[i][j][q] = 0.f;

    const int c0   = tid * 4;
    const int row  = c0 >> 3;
    const int colc = c0 & 7;
    const uint32_t soff = (uint32_t)(row * RS + colc * 8);

    const float* gA = A + (size_t)(m0 + row) * K + colc * 4;
    const float* gB = B + (size_t)(n0 + row) * K + colc * 4;

    const uint32_t aAddr = sAh + (uint32_t)((wm * 64 + (lane & 15)) * RS
                                            + (lane >> 4) * 16);
    const uint32_t bAddr = sBh + (uint32_t)((wn * 32 + ((lane >> 4) & 1) * 8
                                             + (lane & 7)) * RS
                                            + ((lane >> 3) & 1) * 16);

    const int NIT = K / 32;

    float4 pa[4], pb[4];
    #pragma unroll
    for (int i = 0; i < 4; i++) {
        pa[i] = *(const float4*)(gA + i * 4);
        pb[i] = *(const float4*)(gB + i * 4);
    }

    for (int it = 0; it < NIT; ++it) {
        if (it > 0) __syncthreads();

        #pragma unroll
        for (int i = 0; i < 4; i++) {
            uint2 h, l;
            split4(pa[i], h, l);
            sts64(sAh + soff + i * 8, h);
            sts64(sAl + soff + i * 8, l);
            split4(pb[i], h, l);
            sts64(sBh + soff + i * 8, h);
            sts64(sBl + soff + i * 8, l);
        }
        __syncthreads();

        if (it + 1 < NIT) {
            gA += 32; gB += 32;
            #pragma unroll
            for (int i = 0; i < 4; i++) {
                pa[i] = *(const float4*)(gA + i * 4);
                pb[i] = *(const float4*)(gB + i * 4);
            }
        }

        #pragma unroll
        for (int ks = 0; ks < 2; ks++) {
            const uint32_t ko = (uint32_t)(ks * 32);

            uint32_t af[4][4], bh[4][2], bl[4][2];
            #pragma unroll
            for (int mi = 0; mi < 4; mi++)
                ldm_x4(af[mi], aAddr + (uint32_t)(mi * 16 * RS) + ko);
            #pragma unroll
            for (int j2 = 0; j2 < 2; j2++) {
                uint32_t t[4];
                ldm_x4(t, bAddr + (uint32_t)(j2 * 16 * RS) + ko);
                bh[2*j2][0] = t[0]; bh[2*j2][1] = t[1];
                bh[2*j2+1][0] = t[2]; bh[2*j2+1][1] = t[3];
                ldm_x4(t, bAddr + (uint32_t)(TILE_B + j2 * 16 * RS) + ko);
                bl[2*j2][0] = t[0]; bl[2*j2][1] = t[1];
                bl[2*j2+1][0] = t[2]; bl[2*j2+1][1] = t[3];
            }

            #pragma unroll
            for (int mi = 0; mi < 4; mi++)
                #pragma unroll
                for (int nj = 0; nj < 4; nj++)
                    mma_bf16(acc[mi][nj], af[mi], bh[nj][0], bh[nj][1]);
            #pragma unroll
            for (int mi = 0; mi < 4; mi++)
                #pragma unroll
                for (int nj = 0; nj < 4; nj++)
                    mma_bf16(acc[mi][nj], af[mi], bl[nj][0], bl[nj][1]);
            #pragma unroll
            for (int mi = 0; mi < 4; mi++)
                ldm_x4(af[mi], aAddr + (uint32_t)(TILE_B + mi * 16 * RS) + ko);
            #pragma unroll
            for (int mi = 0; mi < 4; mi++)
                #pragma unroll
                for (int nj = 0; nj < 4; nj++)
                    mma_bf16(acc[mi][nj], af[mi], bh[nj][0], bh[nj][1]);
        }
    }

    const int g = lane >> 2;
    const int s = lane & 3;
    #pragma unroll
    for (int mi = 0; mi < 4; mi++) {
        const int mrow = m0 + wm * 64 + mi * 16 + g;
        #pragma unroll
        for (int nj = 0; nj < 4; nj++) {
            const int ncol = n0 + wn * 32 + nj * 8 + s * 2;
            float2 bv = *(const float2*)(bias + ncol);
            float2 o0, o1;
            o0.x = acc[mi][nj][0] + bv.x;  o0.y = acc[mi][nj][1] + bv.y;
            o1.x = acc[mi][nj][2] + bv.x;  o1.y = acc[mi][nj][3] + bv.y;
            *(float2*)(C + (size_t)mrow * N + ncol)       = o0;
            *(float2*)(C + (size_t)(mrow + 8) * N + ncol) = o1;
        }
    }
}

// ===========================================================================
// Flash attention, causal, fp32 (unchanged; proven rel_err 1.2e-6).
// ===========================================================================
#define FA_STRIDE 65

__global__ void __launch_bounds__(256)
flash_attn(const float* __restrict__ qkv, float* __restrict__ out)
{
    extern __shared__ float sm[];
    float* Qs = sm;
    float* Ks = sm + 1 * 64 * FA_STRIDE;
    float* Vs = sm + 2 * 64 * FA_STRIDE;
    float* Ps = sm + 3 * 64 * FA_STRIDE;

    const int iq  = (int)gridDim.x - 1 - (int)blockIdx.x;
    const int h   = blockIdx.y;
    const int b   = blockIdx.z;
    const int tid = threadIdx.x;
    const int tx  = tid & 15;
    const int ty  = tid >> 4;

    const float* base = qkv + (size_t)b * TT * NQKV + h * (3 * HDIM);

    #pragma unroll
    for (int it = 0; it < 4; it++) {
        int f  = tid + it * 256;
        int s  = f >> 4;
        int c4 = f & 15;
        float4 v = *(const float4*)(base + (size_t)(iq * 64 + s) * NQKV + c4 * 4);
        float* q = Qs + s * FA_STRIDE + c4 * 4;
        q[0] = v.x; q[1] = v.y; q[2] = v.z; q[3] = v.w;
    }

    float m[4], l[4], o[4][4];
    #pragma unroll
    for (int r = 0; r < 4; r++) {
        m[r] = -1e30f; l[r] = 0.f;
        #pragma unroll
        for (int c = 0; c < 4; c++) o[r][c] = 0.f;
    }

    for (int j = 0; j <= iq; j++) {
        __syncthreads();
        #pragma unroll
        for (int it = 0; it < 4; it++) {
            int f  = tid + it * 256;
            int s  = f >> 4;
            int c4 = f & 15;
            const float* kp = base + (size_t)(j * 64 + s) * NQKV + HDIM + c4 * 4;
            float4 kv = *(const float4*)kp;
            float4 vv = *(const float4*)(kp + HDIM);
            float* kd = Ks + s * FA_STRIDE + c4 * 4;
            kd[0] = kv.x; kd[1] = kv.y; kd[2] = kv.z; kd[3] = kv.w;
            float* vd = Vs + s * FA_STRIDE + c4 * 4;
            vd[0] = vv.x; vd[1] = vv.y; vd[2] = vv.z; vd[3] = vv.w;
        }
        __syncthreads();

        float sacc[4][4];
        #pragma unroll
        for (int r = 0; r < 4; r++)
            #pragma unroll
            for (int c = 0; c < 4; c++) sacc[r][c] = 0.f;

        #pragma unroll 8
        for (int k = 0; k < 64; k++) {
            float qv[4], kv[4];
            #pragma unroll
            for (int r = 0; r < 4; r++) qv[r] = Qs[(ty * 4 + r) * FA_STRIDE + k];
            #pragma unroll
            for (int c = 0; c < 4; c++) kv[c] = Ks[(tx * 4 + c) * FA_STRIDE + k];
            #pragma unroll
            for (int r = 0; r < 4; r++)
                #pragma unroll
                for (int c = 0; c < 4; c++) sacc[r][c] += qv[r] * kv[c];
        }

        const bool diag = (j == iq);
        #pragma unroll
        for (int r = 0; r < 4; r++)
            #pragma unroll
            for (int c = 0; c < 4; c++) {
                float v = sacc[r][c] * 0.125f;
                if (diag && (tx * 4 + c) > (ty * 4 + r)) v = -1e30f;
                sacc[r][c] = v;
            }

        #pragma unroll
        for (int r = 0; r < 4; r++) {
            float rmax = fmaxf(fmaxf(sacc[r][0], sacc[r][1]),
                               fmaxf(sacc[r][2], sacc[r][3]));
            #pragma unroll
            for (int off = 8; off > 0; off >>= 1)
                rmax = fmaxf(rmax, __shfl_xor_sync(0xffffffffu, rmax, off));

            float mn   = fmaxf(m[r], rmax);
            float corr = __expf(m[r] - mn);

            float rs = 0.f;
            #pragma unroll
            for (int c = 0; c < 4; c++) {
                float p = __expf(sacc[r][c] - mn);
                sacc[r][c] = p;
                rs += p;
            }
            #pragma unroll
            for (int off = 8; off > 0; off >>= 1)
                rs += __shfl_xor_sync(0xffffffffu, rs, off);

            l[r] = l[r] * corr + rs;
            #pragma unroll
            for (int c = 0; c < 4; c++) o[r][c] *= corr;
            m[r] = mn;

            float* pd = Ps + (ty * 4 + r) * FA_STRIDE + tx * 4;
            pd[0] = sacc[r][0]; pd[1] = sacc[r][1];
            pd[2] = sacc[r][2]; pd[3] = sacc[r][3];
        }
        __syncthreads();

        #pragma unroll 8
        for (int s = 0; s < 64; s++) {
            float pv[4], vv[4];
            #pragma unroll
            for (int r = 0; r < 4; r++) pv[r] = Ps[(ty * 4 + r) * FA_STRIDE + s];
            #pragma unroll
            for (int c = 0; c < 4; c++) vv[c] = Vs[s * FA_STRIDE + tx * 4 + c];
            #pragma unroll
            for (int r = 0; r < 4; r++)
                #pragma unroll
                for (int c = 0; c < 4; c++) o[r][c] += pv[r] * vv[c];
        }
    }

    #pragma unroll
    for (int r = 0; r < 4; r++) {
        float inv = 1.f / l[r];
        float* op = out + ((size_t)b * TT + iq * 64 + ty * 4 + r) * DD + h * HDIM + tx * 4;
        *(float4*)op = make_float4(o[r][0] * inv, o[r][1] * inv,
                                   o[r][2] * inv, o[r][3] * inv);
    }
}

// ===========================================================================
// Launch: qkv GEMM (bf16x3 mma.sync) -> flash attention -> out GEMM.
// ===========================================================================
extern "C" void kernel_launch(void* const* d_in, const int* in_sizes, int n_in,
                              void* d_out, int out_size)
{
    const float* x    = (const float*)d_in[0];
    const float* Wqkv = (const float*)d_in[1];
    const float* bqkv = (const float*)d_in[2];
    const float* Wout = (const float*)d_in[3];
    const float* bout = (const float*)d_in[4];
    float*       out  = (float*)d_out;

    float* qkvbuf  = nullptr;
    float* attnbuf = nullptr;
    cudaGetSymbolAddress((void**)&qkvbuf,  g_qkv);
    cudaGetSymbolAddress((void**)&attnbuf, g_attn);

    cudaFuncSetAttribute(bf16x3_gemm_nt_bias,
                         cudaFuncAttributeMaxDynamicSharedMemorySize, GK_SMEM);
    const int fa_smem = 4 * 64 * FA_STRIDE * (int)sizeof(float);
    cudaFuncSetAttribute(flash_attn,
                         cudaFuncAttributeMaxDynamicSharedMemorySize, fa_smem);

    {
        dim3 grid(NQKV / 128, MROWS / 128);   // (24, 32)
        bf16x3_gemm_nt_bias<<<grid, 256, GK_SMEM>>>(x, Wqkv, bqkv, qkvbuf,
                                                    MROWS, NQKV, DD);
    }
    {
        dim3 grid(TT / 64, HH, BB);           // (32, 16, 2)
        flash_attn<<<grid, 256, fa_smem>>>(qkvbuf, attnbuf);
    }
    {
        dim3 grid(DD / 128, MROWS / 128);     // (8, 32)
        bf16x3_gemm_nt_bias<<<grid, 256, GK_SMEM>>>(attnbuf, Wout, bout, out,
                                                    MROWS, DD, DD);
    }
}

// round 9
// speedup vs baseline: 2.1065x; 1.5166x over previous
#include <cuda_runtime.h>
#include <cstdint>

// Problem constants (fixed by the dataset instance)
#define BB    2
#define TT    2048
#define DD    1024
#define HH    16
#define HDIM  64
#define NQKV  (3*DD)          // 3072
#define MROWS (BB*TT)         // 4096

// Scratch (allocation-free rule: __device__ globals)
__device__ float g_qkv[(size_t)MROWS * NQKV];   // [B*T, 3D]
__device__ float g_attn[(size_t)MROWS * DD];    // [B*T, D]

// ===========================================================================
// Baseline-PTX helpers (no sm_103a-gated instructions).
// ===========================================================================
__device__ __forceinline__ uint32_t smem_u32(const void* p) {
    uint32_t a;
    asm("{ .reg .u64 t; cvta.to.shared.u64 t, %1; cvt.u32.u64 %0, t; }"
        : "=r"(a) : "l"(p));
    return a;
}

__device__ __forceinline__ void ldm_x4(uint32_t r[4], uint32_t addr) {
    asm volatile("ldmatrix.sync.aligned.m8n8.x4.shared.b16 {%0,%1,%2,%3}, [%4];"
                 : "=r"(r[0]), "=r"(r[1]), "=r"(r[2]), "=r"(r[3]) : "r"(addr));
}

__device__ __forceinline__ void ldm_x4_t(uint32_t r[4], uint32_t addr) {
    asm volatile("ldmatrix.sync.aligned.m8n8.x4.trans.shared.b16 {%0,%1,%2,%3}, [%4];"
                 : "=r"(r[0]), "=r"(r[1]), "=r"(r[2]), "=r"(r[3]) : "r"(addr));
}

__device__ __forceinline__ void mma_bf16(float c[4], const uint32_t a[4],
                                         uint32_t b0, uint32_t b1) {
    asm volatile(
        "mma.sync.aligned.m16n8k16.row.col.f32.bf16.bf16.f32 "
        "{%0,%1,%2,%3}, {%4,%5,%6,%7}, {%8,%9}, {%0,%1,%2,%3};"
        : "+f"(c[0]), "+f"(c[1]), "+f"(c[2]), "+f"(c[3])
        : "r"(a[0]), "r"(a[1]), "r"(a[2]), "r"(a[3]), "r"(b0), "r"(b1));
}

// pack two floats into bf16x2: first arg -> LOW 16 bits (even-k element)
__device__ __forceinline__ uint32_t packbf(float lo, float hi) {
    uint32_t r;
    asm("cvt.rn.bf16x2.f32 %0, %1, %2;" : "=r"(r) : "f"(hi), "f"(lo));
    return r;
}

// residual (lo) pair for a given hi-pack
__device__ __forceinline__ uint32_t lo_pack(uint32_t hpk, float f0, float f1) {
    float h0 = __uint_as_float(hpk << 16);
    float h1 = __uint_as_float(hpk & 0xffff0000u);
    return packbf(f0 - h0, f1 - h1);
}

// split float4 (4 consecutive k) into hi-pair / lo-pair bf16x2 words
__device__ __forceinline__ void split4(float4 v, uint2& h, uint2& l) {
    h.x = packbf(v.x, v.y);
    h.y = packbf(v.z, v.w);
    l.x = lo_pack(h.x, v.x, v.y);
    l.y = lo_pack(h.y, v.z, v.w);
}

__device__ __forceinline__ void sts64(uint32_t addr, uint2 v) {
    asm volatile("st.shared.v2.b32 [%0], {%1,%2};"
                 :: "r"(addr), "r"(v.x), "r"(v.y) : "memory");
}

// ===========================================================================
// 3x-BF16 tensor-core GEMM (double-buffered): C = A @ B^T + bias
// CTA 128x128, 8 warps, K-step 32, fp32 accumulate. 2 smem stages.
// ===========================================================================
#define RS 80
#define TILE_B (128 * RS)          // 10240 B per tile
#define STAGE_B (4 * TILE_B)       // Ah,Al,Bh,Bl
#define GK_SMEM (2 * STAGE_B + 128)

__global__ void __launch_bounds__(256)
bf16x3_gemm_nt_bias(const float* __restrict__ A, const float* __restrict__ B,
                    const float* __restrict__ bias, float* __restrict__ C,
                    int M, int N, int K)
{
    extern __shared__ char smem[];
    const uint32_t sb  = (smem_u32(smem) + 127) & ~127u;

    const int tid  = threadIdx.x;
    const int lane = tid & 31;
    const int wid  = tid >> 5;
    const int wm   = wid & 1;
    const int wn   = wid >> 1;
    const int m0   = blockIdx.y * 128;
    const int n0   = blockIdx.x * 128;

    float acc[4][4][4];
    #pragma unroll
    for (int i = 0; i < 4; i++)
        #pragma unroll
        for (int j = 0; j < 4; j++)
            #pragma unroll
            for (int q = 0; q < 4; q++) acc[i][j][q] = 0.f;

    const int c0   = tid * 4;
    const int row  = c0 >> 3;
    const int colc = c0 & 7;
    const uint32_t soff = (uint32_t)(row * RS + colc * 8);

    const float* gA = A + (size_t)(m0 + row) * K + colc * 4;
    const float* gB = B + (size_t)(n0 + row) * K + colc * 4;

    const uint32_t aLane = (uint32_t)((wm * 64 + (lane & 15)) * RS
                                      + (lane >> 4) * 16);
    const uint32_t bLane = (uint32_t)((wn * 32 + ((lane >> 4) & 1) * 8
                                       + (lane & 7)) * RS
                                      + ((lane >> 3) & 1) * 16);

    const int NIT = K / 32;

    float4 pa[4], pb[4];
    #pragma unroll
    for (int i = 0; i < 4; i++) {
        pa[i] = *(const float4*)(gA + i * 4);
        pb[i] = *(const float4*)(gB + i * 4);
    }
    // store stage 0
    #pragma unroll
    for (int i = 0; i < 4; i++) {
        uint2 h, l;
        split4(pa[i], h, l);
        sts64(sb + soff + i * 8, h);
        sts64(sb + TILE_B + soff + i * 8, l);
        split4(pb[i], h, l);
        sts64(sb + 2 * TILE_B + soff + i * 8, h);
        sts64(sb + 3 * TILE_B + soff + i * 8, l);
    }

    for (int it = 0; it < NIT; ++it) {
        const bool more = (it + 1 < NIT);
        if (more) {
            gA += 32; gB += 32;
            #pragma unroll
            for (int i = 0; i < 4; i++) {
                pa[i] = *(const float4*)(gA + i * 4);
                pb[i] = *(const float4*)(gB + i * 4);
            }
        }
        __syncthreads();   // stage (it&1) visible; stage ((it+1)&1) free

        if (more) {
            const uint32_t st = sb + (uint32_t)(((it + 1) & 1) * STAGE_B);
            #pragma unroll
            for (int i = 0; i < 4; i++) {
                uint2 h, l;
                split4(pa[i], h, l);
                sts64(st + soff + i * 8, h);
                sts64(st + TILE_B + soff + i * 8, l);
                split4(pb[i], h, l);
                sts64(st + 2 * TILE_B + soff + i * 8, h);
                sts64(st + 3 * TILE_B + soff + i * 8, l);
            }
        }

        const uint32_t cur = sb + (uint32_t)((it & 1) * STAGE_B);
        const uint32_t aAddr = cur + aLane;
        const uint32_t bAddr = cur + 2 * TILE_B + bLane;

        #pragma unroll
        for (int ks = 0; ks < 2; ks++) {
            const uint32_t ko = (uint32_t)(ks * 32);

            uint32_t af[4][4], bh[4][2], bl[4][2];
            #pragma unroll
            for (int mi = 0; mi < 4; mi++)
                ldm_x4(af[mi], aAddr + (uint32_t)(mi * 16 * RS) + ko);
            #pragma unroll
            for (int j2 = 0; j2 < 2; j2++) {
                uint32_t t[4];
                ldm_x4(t, bAddr + (uint32_t)(j2 * 16 * RS) + ko);
                bh[2*j2][0] = t[0]; bh[2*j2][1] = t[1];
                bh[2*j2+1][0] = t[2]; bh[2*j2+1][1] = t[3];
                ldm_x4(t, bAddr + (uint32_t)(TILE_B + j2 * 16 * RS) + ko);
                bl[2*j2][0] = t[0]; bl[2*j2][1] = t[1];
                bl[2*j2+1][0] = t[2]; bl[2*j2+1][1] = t[3];
            }

            #pragma unroll
            for (int mi = 0; mi < 4; mi++)
                #pragma unroll
                for (int nj = 0; nj < 4; nj++)
                    mma_bf16(acc[mi][nj], af[mi], bh[nj][0], bh[nj][1]);
            #pragma unroll
            for (int mi = 0; mi < 4; mi++)
                #pragma unroll
                for (int nj = 0; nj < 4; nj++)
                    mma_bf16(acc[mi][nj], af[mi], bl[nj][0], bl[nj][1]);
            #pragma unroll
            for (int mi = 0; mi < 4; mi++)
                ldm_x4(af[mi], aAddr + (uint32_t)(TILE_B + mi * 16 * RS) + ko);
            #pragma unroll
            for (int mi = 0; mi < 4; mi++)
                #pragma unroll
                for (int nj = 0; nj < 4; nj++)
                    mma_bf16(acc[mi][nj], af[mi], bh[nj][0], bh[nj][1]);
        }
    }

    const int g = lane >> 2;
    const int s = lane & 3;
    #pragma unroll
    for (int mi = 0; mi < 4; mi++) {
        const int mrow = m0 + wm * 64 + mi * 16 + g;
        #pragma unroll
        for (int nj = 0; nj < 4; nj++) {
            const int ncol = n0 + wn * 32 + nj * 8 + s * 2;
            float2 bv = *(const float2*)(bias + ncol);
            float2 o0, o1;
            o0.x = acc[mi][nj][0] + bv.x;  o0.y = acc[mi][nj][1] + bv.y;
            o1.x = acc[mi][nj][2] + bv.x;  o1.y = acc[mi][nj][3] + bv.y;
            *(float2*)(C + (size_t)mrow * N + ncol)       = o0;
            *(float2*)(C + (size_t)(mrow + 8) * N + ncol) = o1;
        }
    }
}

// ===========================================================================
// Tensor-core flash attention (causal), 3x-bf16 for S=QK^T and O=PV.
// CTA = 64 q-rows x (head,batch); 4 warps, each owns 16 q-rows.
// Q pre-scaled by 0.125 at load. P stays in registers (C-frag -> A-frag).
// V consumed via ldmatrix.x4.trans (natural [key][hd] smem layout).
// smem per tile: 64 rows x 144B stride (128B data + 16 pad, ldmatrix-clean).
// ===========================================================================
#define AT_RS   144
#define AT_TILE (64 * AT_RS)            // 9216
#define AT_QH   0
#define AT_QL   (1 * AT_TILE)
#define AT_KH   (2 * AT_TILE)
#define AT_KL   (3 * AT_TILE)
#define AT_VH   (4 * AT_TILE)
#define AT_VL   (5 * AT_TILE)
#define AT_SMEM (6 * AT_TILE + 128)     // 55424

__global__ void __launch_bounds__(128)
flash_attn_mma(const float* __restrict__ qkv, float* __restrict__ out)
{
    extern __shared__ char smem[];
    const uint32_t sb = (smem_u32(smem) + 127) & ~127u;

    const int iq   = (int)gridDim.x - 1 - (int)blockIdx.x;   // heavy first
    const int h    = blockIdx.y;
    const int b    = blockIdx.z;
    const int tid  = threadIdx.x;
    const int lane = tid & 31;
    const int w    = tid >> 5;

    const float* base = qkv + (size_t)b * TT * NQKV + h * (3 * HDIM);

    // ---- load Q (scaled by 1/sqrt(hd)=0.125), hi/lo split ----
    #pragma unroll
    for (int itx = 0; itx < 8; itx++) {
        int f  = tid + itx * 128;
        int r  = f >> 4;
        int c4 = f & 15;
        float4 v = *(const float4*)(base + (size_t)(iq * 64 + r) * NQKV + c4 * 4);
        v.x *= 0.125f; v.y *= 0.125f; v.z *= 0.125f; v.w *= 0.125f;
        uint2 hh, ll;
        split4(v, hh, ll);
        const uint32_t off = (uint32_t)(r * AT_RS + c4 * 8);
        sts64(sb + AT_QH + off, hh);
        sts64(sb + AT_QL + off, ll);
    }

    const int g = lane >> 2;
    const int s = lane & 3;

    // ldmatrix lane addresses
    const uint32_t aQ = sb + AT_QH +
        (uint32_t)((w * 16 + (lane & 15)) * AT_RS + (lane >> 4) * 16);
    const uint32_t bK = sb + AT_KH +
        (uint32_t)((((lane >> 4) & 1) * 8 + (lane & 7)) * AT_RS
                   + ((lane >> 3) & 1) * 16);
    const uint32_t bV = sb + AT_VH +
        (uint32_t)((((lane >> 3) & 1) * 8 + (lane & 7)) * AT_RS
                   + ((lane >> 4) & 1) * 16);

    float m0v = -1e30f, m1v = -1e30f, l0v = 0.f, l1v = 0.f;
    float o[8][4];
    #pragma unroll
    for (int nt = 0; nt < 8; nt++)
        #pragma unroll
        for (int q = 0; q < 4; q++) o[nt][q] = 0.f;

    const int qrow0 = iq * 64 + w * 16 + g;   // row of c0/c1 (c2/c3: +8)

    for (int j = 0; j <= iq; j++) {
        __syncthreads();   // previous block's ldmatrix reads done
        // ---- load K, V (hi/lo split); V stays [key][hd] ----
        #pragma unroll
        for (int itx = 0; itx < 8; itx++) {
            int f  = tid + itx * 128;
            int r  = f >> 4;
            int c4 = f & 15;
            const float* kp = base + (size_t)(j * 64 + r) * NQKV + HDIM + c4 * 4;
            float4 kv = *(const float4*)kp;
            float4 vv = *(const float4*)(kp + HDIM);
            const uint32_t off = (uint32_t)(r * AT_RS + c4 * 8);
            uint2 hh, ll;
            split4(kv, hh, ll);
            sts64(sb + AT_KH + off, hh);
            sts64(sb + AT_KL + off, ll);
            split4(vv, hh, ll);
            sts64(sb + AT_VH + off, hh);
            sts64(sb + AT_VL + off, ll);
        }
        __syncthreads();

        // ---- S = Q @ K^T (3-term split, fp32 accum) ----
        float sacc[8][4];
        #pragma unroll
        for (int nt = 0; nt < 8; nt++)
            #pragma unroll
            for (int q = 0; q < 4; q++) sacc[nt][q] = 0.f;

        #pragma unroll
        for (int ks = 0; ks < 4; ks++) {
            const uint32_t ko = (uint32_t)(ks * 32);
            uint32_t qh[4], ql[4];
            ldm_x4(qh, aQ + ko);
            ldm_x4(ql, aQ + (uint32_t)(AT_QL - AT_QH) + ko);
            #pragma unroll
            for (int nb = 0; nb < 4; nb++) {
                uint32_t t[4], tl[4];
                ldm_x4(t,  bK + (uint32_t)(nb * 16 * AT_RS) + ko);
                ldm_x4(tl, bK + (uint32_t)((AT_KL - AT_KH) + nb * 16 * AT_RS) + ko);
                mma_bf16(sacc[2*nb],   qh, t[0],  t[1]);
                mma_bf16(sacc[2*nb+1], qh, t[2],  t[3]);
                mma_bf16(sacc[2*nb],   qh, tl[0], tl[1]);
                mma_bf16(sacc[2*nb+1], qh, tl[2], tl[3]);
                mma_bf16(sacc[2*nb],   ql, t[0],  t[1]);
                mma_bf16(sacc[2*nb+1], ql, t[2],  t[3]);
            }
        }

        // ---- causal mask (diag block only) ----
        if (j == iq) {
            #pragma unroll
            for (int nt = 0; nt < 8; nt++) {
                const int col = j * 64 + nt * 8 + s * 2;
                if (col     > qrow0)     sacc[nt][0] = -1e30f;
                if (col + 1 > qrow0)     sacc[nt][1] = -1e30f;
                if (col     > qrow0 + 8) sacc[nt][2] = -1e30f;
                if (col + 1 > qrow0 + 8) sacc[nt][3] = -1e30f;
            }
        }

        // ---- online softmax on fragments ----
        float mx0 = -1e30f, mx1 = -1e30f;
        #pragma unroll
        for (int nt = 0; nt < 8; nt++) {
            mx0 = fmaxf(mx0, fmaxf(sacc[nt][0], sacc[nt][1]));
            mx1 = fmaxf(mx1, fmaxf(sacc[nt][2], sacc[nt][3]));
        }
        mx0 = fmaxf(mx0, __shfl_xor_sync(0xffffffffu, mx0, 1));
        mx0 = fmaxf(mx0, __shfl_xor_sync(0xffffffffu, mx0, 2));
        mx1 = fmaxf(mx1, __shfl_xor_sync(0xffffffffu, mx1, 1));
        mx1 = fmaxf(mx1, __shfl_xor_sync(0xffffffffu, mx1, 2));

        const float mn0 = fmaxf(m0v, mx0);
        const float mn1 = fmaxf(m1v, mx1);
        const float cr0 = __expf(m0v - mn0);
        const float cr1 = __expf(m1v - mn1);

        float rs0 = 0.f, rs1 = 0.f;
        #pragma unroll
        for (int nt = 0; nt < 8; nt++) {
            float p0 = __expf(sacc[nt][0] - mn0);
            float p1 = __expf(sacc[nt][1] - mn0);
            float p2 = __expf(sacc[nt][2] - mn1);
            float p3 = __expf(sacc[nt][3] - mn1);
            sacc[nt][0] = p0; sacc[nt][1] = p1;
            sacc[nt][2] = p2; sacc[nt][3] = p3;
            rs0 += p0 + p1;
            rs1 += p2 + p3;
        }
        rs0 += __shfl_xor_sync(0xffffffffu, rs0, 1);
        rs0 += __shfl_xor_sync(0xffffffffu, rs0, 2);
        rs1 += __shfl_xor_sync(0xffffffffu, rs1, 1);
        rs1 += __shfl_xor_sync(0xffffffffu, rs1, 2);

        l0v = l0v * cr0 + rs0;
        l1v = l1v * cr1 + rs1;
        m0v = mn0;
        m1v = mn1;
        #pragma unroll
        for (int nt = 0; nt < 8; nt++) {
            o[nt][0] *= cr0; o[nt][1] *= cr0;
            o[nt][2] *= cr1; o[nt][3] *= cr1;
        }

        // ---- O += P @ V (3-term; P from registers, V via ldmatrix.trans) ----
        #pragma unroll
        for (int ks = 0; ks < 4; ks++) {
            uint32_t ph[4], pl[4];
            ph[0] = packbf(sacc[2*ks][0],   sacc[2*ks][1]);
            ph[1] = packbf(sacc[2*ks][2],   sacc[2*ks][3]);
            ph[2] = packbf(sacc[2*ks+1][0], sacc[2*ks+1][1]);
            ph[3] = packbf(sacc[2*ks+1][2], sacc[2*ks+1][3]);
            pl[0] = lo_pack(ph[0], sacc[2*ks][0],   sacc[2*ks][1]);
            pl[1] = lo_pack(ph[1], sacc[2*ks][2],   sacc[2*ks][3]);
            pl[2] = lo_pack(ph[2], sacc[2*ks+1][0], sacc[2*ks+1][1]);
            pl[3] = lo_pack(ph[3], sacc[2*ks+1][2], sacc[2*ks+1][3]);

            const uint32_t krow = (uint32_t)(ks * 16 * AT_RS);
            #pragma unroll
            for (int nb = 0; nb < 4; nb++) {
                uint32_t t[4], tl[4];
                ldm_x4_t(t,  bV + krow + (uint32_t)(nb * 32));
                ldm_x4_t(tl, bV + (uint32_t)(AT_VL - AT_VH) + krow
                             + (uint32_t)(nb * 32));
                mma_bf16(o[2*nb],   ph, t[0],  t[1]);
                mma_bf16(o[2*nb+1], ph, t[2],  t[3]);
                mma_bf16(o[2*nb],   ph, tl[0], tl[1]);
                mma_bf16(o[2*nb+1], ph, tl[2], tl[3]);
                mma_bf16(o[2*nb],   pl, t[0],  t[1]);
                mma_bf16(o[2*nb+1], pl, t[2],  t[3]);
            }
        }
    }

    // ---- epilogue: normalize and write [B,T,H*hd] ----
    const float inv0 = 1.f / l0v;
    const float inv1 = 1.f / l1v;
    const size_t row0 = (size_t)b * TT + iq * 64 + w * 16 + g;
    #pragma unroll
    for (int nt = 0; nt < 8; nt++) {
        const int col = h * HDIM + nt * 8 + s * 2;
        float2 v0, v1;
        v0.x = o[nt][0] * inv0;  v0.y = o[nt][1] * inv0;
        v1.x = o[nt][2] * inv1;  v1.y = o[nt][3] * inv1;
        *(float2*)(out + row0 * DD + col)       = v0;
        *(float2*)(out + (row0 + 8) * DD + col) = v1;
    }
}

// ===========================================================================
// Launch: qkv GEMM -> tensor-core flash attention -> out GEMM.
// ===========================================================================
extern "C" void kernel_launch(void* const* d_in, const int* in_sizes, int n_in,
                              void* d_out, int out_size)
{
    const float* x    = (const float*)d_in[0];
    const float* Wqkv = (const float*)d_in[1];
    const float* bqkv = (const float*)d_in[2];
    const float* Wout = (const float*)d_in[3];
    const float* bout = (const float*)d_in[4];
    float*       out  = (float*)d_out;

    float* qkvbuf  = nullptr;
    float* attnbuf = nullptr;
    cudaGetSymbolAddress((void**)&qkvbuf,  g_qkv);
    cudaGetSymbolAddress((void**)&attnbuf, g_attn);

    cudaFuncSetAttribute(bf16x3_gemm_nt_bias,
                         cudaFuncAttributeMaxDynamicSharedMemorySize, GK_SMEM);
    cudaFuncSetAttribute(flash_attn_mma,
                         cudaFuncAttributeMaxDynamicSharedMemorySize, AT_SMEM);

    {
        dim3 grid(NQKV / 128, MROWS / 128);   // (24, 32)
        bf16x3_gemm_nt_bias<<<grid, 256, GK_SMEM>>>(x, Wqkv, bqkv, qkvbuf,
                                                    MROWS, NQKV, DD);
    }
    {
        dim3 grid(TT / 64, HH, BB);           // (32, 16, 2)
        flash_attn_mma<<<grid, 128, AT_SMEM>>>(qkvbuf, attnbuf);
    }
    {
        dim3 grid(DD / 128, MROWS / 128);     // (8, 32)
        bf16x3_gemm_nt_bias<<<grid, 256, GK_SMEM>>>(attnbuf, Wout, bout, out,
                                                    MROWS, DD, DD);
    }
}

// round 11
// speedup vs baseline: 2.7478x; 1.3045x over previous
#include <cuda_runtime.h>
#include <cstdint>

// Problem constants (fixed by the dataset instance)
#define BB    2
#define TT    2048
#define DD    1024
#define HH    16
#define HDIM  64
#define NQKV  (3*DD)          // 3072
#define MROWS (BB*TT)         // 4096
#define DW    (DD/2)          // u32 words per D-wide row (512)
#define QW    (NQKV/2)        // u32 words per qkv row (1536)

// Scratch (allocation-free rule: __device__ globals). All bf16x2-packed (u32).
__device__ uint32_t g_xh [(size_t)MROWS * DW], g_xl [(size_t)MROWS * DW];
__device__ uint32_t g_wqh[(size_t)NQKV  * DW], g_wql[(size_t)NQKV  * DW];
__device__ uint32_t g_woh[(size_t)DD    * DW], g_wol[(size_t)DD    * DW];
__device__ uint32_t g_qh [(size_t)MROWS * QW], g_ql [(size_t)MROWS * QW];
__device__ uint32_t g_ah [(size_t)MROWS * DW], g_al [(size_t)MROWS * DW];

// ===========================================================================
// Baseline-PTX helpers (no sm_103a-gated instructions).
// ===========================================================================
__device__ __forceinline__ uint32_t smem_u32(const void* p) {
    uint32_t a;
    asm("{ .reg .u64 t; cvta.to.shared.u64 t, %1; cvt.u32.u64 %0, t; }"
        : "=r"(a) : "l"(p));
    return a;
}

__device__ __forceinline__ void ldm_x4(uint32_t r[4], uint32_t addr) {
    asm volatile("ldmatrix.sync.aligned.m8n8.x4.shared.b16 {%0,%1,%2,%3}, [%4];"
                 : "=r"(r[0]), "=r"(r[1]), "=r"(r[2]), "=r"(r[3]) : "r"(addr));
}

__device__ __forceinline__ void ldm_x4_t(uint32_t r[4], uint32_t addr) {
    asm volatile("ldmatrix.sync.aligned.m8n8.x4.trans.shared.b16 {%0,%1,%2,%3}, [%4];"
                 : "=r"(r[0]), "=r"(r[1]), "=r"(r[2]), "=r"(r[3]) : "r"(addr));
}

__device__ __forceinline__ void mma_bf16(float c[4], const uint32_t a[4],
                                         uint32_t b0, uint32_t b1) {
    asm volatile(
        "mma.sync.aligned.m16n8k16.row.col.f32.bf16.bf16.f32 "
        "{%0,%1,%2,%3}, {%4,%5,%6,%7}, {%8,%9}, {%0,%1,%2,%3};"
        : "+f"(c[0]), "+f"(c[1]), "+f"(c[2]), "+f"(c[3])
        : "r"(a[0]), "r"(a[1]), "r"(a[2]), "r"(a[3]), "r"(b0), "r"(b1));
}

// pack two floats into bf16x2: first arg -> LOW 16 bits (even-k element)
__device__ __forceinline__ uint32_t packbf(float lo, float hi) {
    uint32_t r;
    asm("cvt.rn.bf16x2.f32 %0, %1, %2;" : "=r"(r) : "f"(hi), "f"(lo));
    return r;
}

__device__ __forceinline__ uint32_t lo_pack(uint32_t hpk, float f0, float f1) {
    float h0 = __uint_as_float(hpk << 16);
    float h1 = __uint_as_float(hpk & 0xffff0000u);
    return packbf(f0 - h0, f1 - h1);
}

__device__ __forceinline__ void split4(float4 v, uint2& h, uint2& l) {
    h.x = packbf(v.x, v.y);
    h.y = packbf(v.z, v.w);
    l.x = lo_pack(h.x, v.x, v.y);
    l.y = lo_pack(h.y, v.z, v.w);
}

__device__ __forceinline__ void cp16(uint32_t dst, const uint32_t* src) {
    asm volatile("cp.async.cg.shared.global [%0], [%1], 16;"
                 :: "r"(dst), "l"(src) : "memory");
}
__device__ __forceinline__ void cp_commit() {
    asm volatile("cp.async.commit_group;" ::: "memory");
}
__device__ __forceinline__ void cp_wait0() {
    asm volatile("cp.async.wait_group 0;" ::: "memory");
}

// ===========================================================================
// Pre-pass: split fp32 matrix into bf16 hi/lo (packed u32 pairs).
// ===========================================================================
__global__ void split_f32(const float4* __restrict__ src, uint2* __restrict__ h,
                          uint2* __restrict__ l, int n4)
{
    int i = blockIdx.x * 256 + threadIdx.x;
    if (i < n4) {
        uint2 hh, ll;
        split4(src[i], hh, ll);
        h[i] = hh;
        l[i] = ll;
    }
}

// ===========================================================================
// bf16x3 tensor-core GEMM, cp.async 2-stage pipeline, pre-split inputs.
// C[M,N] = A[M,K] @ B[N,K]^T + bias[N]; A,B given as hi/lo bf16 (u32-packed).
// CTA 128x128, 8 warps (warp tile 64x32), K-step 32, fp32 accumulate.
// split_out=1: write C as hi/lo bf16 (u32-packed). split_out=0: fp32 C32.
// ===========================================================================
#define RS 80
#define TILE_B (128 * RS)          // 10240
#define STAGE_B (4 * TILE_B)       // Ah,Al,Bh,Bl
#define GK_SMEM (2 * STAGE_B + 128)

__global__ void __launch_bounds__(256, 2)
bf16x3_gemm_async(const uint32_t* __restrict__ Ah, const uint32_t* __restrict__ Al,
                  const uint32_t* __restrict__ Bh, const uint32_t* __restrict__ Bl,
                  const float* __restrict__ bias,
                  float* __restrict__ C32,
                  uint32_t* __restrict__ Ch, uint32_t* __restrict__ Cl,
                  int M, int N, int K, int split_out)
{
    extern __shared__ char smem[];
    const uint32_t sb = (smem_u32(smem) + 127) & ~127u;

    const int tid  = threadIdx.x;
    const int lane = tid & 31;
    const int wid  = tid >> 5;
    const int wm   = wid & 1;
    const int wn   = wid >> 1;
    const int m0   = blockIdx.y * 128;
    const int n0   = blockIdx.x * 128;
    const int Kw   = K >> 1;          // u32 words per row

    float acc[4][4][4];
    #pragma unroll
    for (int i = 0; i < 4; i++)
        #pragma unroll
        for (int j = 0; j < 4; j++)
            #pragma unroll
            for (int q = 0; q < 4; q++) acc[i][j][q] = 0.f;

    // Each thread copies one 32B half-row per tile per stage.
    const int row  = tid >> 1;
    const int half = tid & 1;
    const uint32_t soff = (uint32_t)(row * RS + half * 32);

    const uint32_t* gAh = Ah + (size_t)(m0 + row) * Kw + half * 8;
    const uint32_t* gAl = Al + (size_t)(m0 + row) * Kw + half * 8;
    const uint32_t* gBh = Bh + (size_t)(n0 + row) * Kw + half * 8;
    const uint32_t* gBl = Bl + (size_t)(n0 + row) * Kw + half * 8;

    const uint32_t aLane = (uint32_t)((wm * 64 + (lane & 15)) * RS
                                      + (lane >> 4) * 16);
    const uint32_t bLane = (uint32_t)((wn * 32 + ((lane >> 4) & 1) * 8
                                       + (lane & 7)) * RS
                                      + ((lane >> 3) & 1) * 16);

    const int NIT = K / 32;

    // issue stage 0 (k0 = 0)
    {
        const uint32_t d = sb + soff;
        cp16(d,                  gAh); cp16(d + 16,              gAh + 4);
        cp16(d + TILE_B,         gAl); cp16(d + TILE_B + 16,     gAl + 4);
        cp16(d + 2 * TILE_B,     gBh); cp16(d + 2 * TILE_B + 16, gBh + 4);
        cp16(d + 3 * TILE_B,     gBl); cp16(d + 3 * TILE_B + 16, gBl + 4);
        cp_commit();
    }

    for (int it = 0; it < NIT; ++it) {
        cp_wait0();
        __syncthreads();

        if (it + 1 < NIT) {
            const uint32_t d  = sb + (uint32_t)(((it + 1) & 1) * STAGE_B) + soff;
            const int      ko = (it + 1) * 16;   // u32 offset along K
            cp16(d,                  gAh + ko); cp16(d + 16,              gAh + ko + 4);
            cp16(d + TILE_B,         gAl + ko); cp16(d + TILE_B + 16,     gAl + ko + 4);
            cp16(d + 2 * TILE_B,     gBh + ko); cp16(d + 2 * TILE_B + 16, gBh + ko + 4);
            cp16(d + 3 * TILE_B,     gBl + ko); cp16(d + 3 * TILE_B + 16, gBl + ko + 4);
            cp_commit();
        }

        const uint32_t cur   = sb + (uint32_t)((it & 1) * STAGE_B);
        const uint32_t aAddr = cur + aLane;
        const uint32_t bAddr = cur + 2 * TILE_B + bLane;

        #pragma unroll
        for (int ks = 0; ks < 2; ks++) {
            const uint32_t ko = (uint32_t)(ks * 32);

            uint32_t af[4][4], bh[4][2], bl[4][2];
            #pragma unroll
            for (int mi = 0; mi < 4; mi++)
                ldm_x4(af[mi], aAddr + (uint32_t)(mi * 16 * RS) + ko);
            #pragma unroll
            for (int j2 = 0; j2 < 2; j2++) {
                uint32_t t[4];
                ldm_x4(t, bAddr + (uint32_t)(j2 * 16 * RS) + ko);
                bh[2*j2][0] = t[0]; bh[2*j2][1] = t[1];
                bh[2*j2+1][0] = t[2]; bh[2*j2+1][1] = t[3];
                ldm_x4(t, bAddr + (uint32_t)(TILE_B + j2 * 16 * RS) + ko);
                bl[2*j2][0] = t[0]; bl[2*j2][1] = t[1];
                bl[2*j2+1][0] = t[2]; bl[2*j2+1][1] = t[3];
            }

            #pragma unroll
            for (int mi = 0; mi < 4; mi++)
                #pragma unroll
                for (int nj = 0; nj < 4; nj++)
                    mma_bf16(acc[mi][nj], af[mi], bh[nj][0], bh[nj][1]);
            #pragma unroll
            for (int mi = 0; mi < 4; mi++)
                #pragma unroll
                for (int nj = 0; nj < 4; nj++)
                    mma_bf16(acc[mi][nj], af[mi], bl[nj][0], bl[nj][1]);
            #pragma unroll
            for (int mi = 0; mi < 4; mi++)
                ldm_x4(af[mi], aAddr + (uint32_t)(TILE_B + mi * 16 * RS) + ko);
            #pragma unroll
            for (int mi = 0; mi < 4; mi++)
                #pragma unroll
                for (int nj = 0; nj < 4; nj++)
                    mma_bf16(acc[mi][nj], af[mi], bh[nj][0], bh[nj][1]);
        }
    }

    const int g = lane >> 2;
    const int s = lane & 3;
    if (split_out) {
        const int Nw = N >> 1;
        #pragma unroll
        for (int mi = 0; mi < 4; mi++) {
            const int mrow = m0 + wm * 64 + mi * 16 + g;
            #pragma unroll
            for (int nj = 0; nj < 4; nj++) {
                const int ncol = n0 + wn * 32 + nj * 8 + s * 2;
                float2 bv = *(const float2*)(bias + ncol);
                float v0 = acc[mi][nj][0] + bv.x;
                float v1 = acc[mi][nj][1] + bv.y;
                float v2 = acc[mi][nj][2] + bv.x;
                float v3 = acc[mi][nj][3] + bv.y;
                uint32_t hw0 = packbf(v0, v1);
                uint32_t hw1 = packbf(v2, v3);
                const size_t i0 = (size_t)mrow * Nw + (ncol >> 1);
                const size_t i1 = (size_t)(mrow + 8) * Nw + (ncol >> 1);
                Ch[i0] = hw0;  Cl[i0] = lo_pack(hw0, v0, v1);
                Ch[i1] = hw1;  Cl[i1] = lo_pack(hw1, v2, v3);
            }
        }
    } else {
        #pragma unroll
        for (int mi = 0; mi < 4; mi++) {
            const int mrow = m0 + wm * 64 + mi * 16 + g;
            #pragma unroll
            for (int nj = 0; nj < 4; nj++) {
                const int ncol = n0 + wn * 32 + nj * 8 + s * 2;
                float2 bv = *(const float2*)(bias + ncol);
                float2 o0, o1;
                o0.x = acc[mi][nj][0] + bv.x;  o0.y = acc[mi][nj][1] + bv.y;
                o1.x = acc[mi][nj][2] + bv.x;  o1.y = acc[mi][nj][3] + bv.y;
                *(float2*)(C32 + (size_t)mrow * N + ncol)       = o0;
                *(float2*)(C32 + (size_t)(mrow + 8) * N + ncol) = o1;
            }
        }
    }
}

// ===========================================================================
// Tensor-core flash attention (causal), pre-split bf16 inputs, cp.async
// double-buffered K/V. CTA = 64 q-rows x (head,batch); 4 warps.
// S scaled by 0.125 post-MMA. P register path as round 9 (validated).
// Epilogue writes attn as hi/lo bf16 (u32-packed).
// ===========================================================================
#define AT_RS   144
#define AT_TILE (64 * AT_RS)                 // 9216
#define AT_QH   0
#define AT_QL   (1 * AT_TILE)
#define AT_KV0  (2 * AT_TILE)                // stage s at AT_KV0 + s*4*AT_TILE
#define AT_SMEM ((2 + 8) * AT_TILE + 128)    // 92288

__global__ void __launch_bounds__(128)
flash_attn_mma(const uint32_t* __restrict__ qh, const uint32_t* __restrict__ ql,
               uint32_t* __restrict__ ah, uint32_t* __restrict__ al)
{
    extern __shared__ char smem[];
    const uint32_t sb = (smem_u32(smem) + 127) & ~127u;

    const int iq   = (int)gridDim.x - 1 - (int)blockIdx.x;   // heavy first
    const int h    = blockIdx.y;
    const int b    = blockIdx.z;
    const int tid  = threadIdx.x;
    const int lane = tid & 31;
    const int w    = tid >> 5;

    const uint32_t* baseh = qh + (size_t)b * TT * QW + h * 96;  // h*192 bf16
    const uint32_t* basel = ql + (size_t)b * TT * QW + h * 96;

    // cp.async copy geometry: 512 chunks (16B) per 64x128B tile.
    // chunk f: row r = f>>3 (0..63), col c = f&7.
    auto issueQ = [&]() {
        #pragma unroll
        for (int itx = 0; itx < 4; itx++) {
            const int f = tid + itx * 128;
            const int r = f >> 3, c = f & 7;
            const size_t go = (size_t)(iq * 64 + r) * QW + c * 4;
            const uint32_t off = (uint32_t)(r * AT_RS + c * 16);
            cp16(sb + AT_QH + off, baseh + go);
            cp16(sb + AT_QL + off, basel + go);
        }
    };
    auto issueKV = [&](int j, int stg) {
        const uint32_t st = sb + AT_KV0 + (uint32_t)(stg * 4 * AT_TILE);
        #pragma unroll
        for (int itx = 0; itx < 4; itx++) {
            const int f = tid + itx * 128;
            const int r = f >> 3, c = f & 7;
            const size_t go = (size_t)(j * 64 + r) * QW + 32 + c * 4;  // K at +64 bf16
            const uint32_t off = (uint32_t)(r * AT_RS + c * 16);
            cp16(st + off,               baseh + go);        // Kh
            cp16(st + AT_TILE + off,     basel + go);        // Kl
            cp16(st + 2 * AT_TILE + off, baseh + go + 32);   // Vh (+64 bf16)
            cp16(st + 3 * AT_TILE + off, basel + go + 32);   // Vl
        }
    };

    issueQ();
    issueKV(0, 0);
    cp_commit();

    const int g = lane >> 2;
    const int s = lane & 3;

    const uint32_t aQ = sb + AT_QH +
        (uint32_t)((w * 16 + (lane & 15)) * AT_RS + (lane >> 4) * 16);
    const uint32_t kLane =
        (uint32_t)((((lane >> 4) & 1) * 8 + (lane & 7)) * AT_RS
                   + ((lane >> 3) & 1) * 16);
    const uint32_t vLane =
        (uint32_t)((((lane >> 3) & 1) * 8 + (lane & 7)) * AT_RS
                   + ((lane >> 4) & 1) * 16);

    float m0v = -1e30f, m1v = -1e30f, l0v = 0.f, l1v = 0.f;
    float o[8][4];
    #pragma unroll
    for (int nt = 0; nt < 8; nt++)
        #pragma unroll
        for (int q = 0; q < 4; q++) o[nt][q] = 0.f;

    const int qrow0 = iq * 64 + w * 16 + g;

    for (int j = 0; j <= iq; j++) {
        const int cur = j & 1;
        cp_wait0();
        __syncthreads();          // all warps done reading stage cur^1 (iter j-1)
        if (j < iq) {
            issueKV(j + 1, cur ^ 1);
            cp_commit();
        }

        const uint32_t st = sb + AT_KV0 + (uint32_t)(cur * 4 * AT_TILE);
        const uint32_t bK = st + kLane;
        const uint32_t bV = st + 2 * AT_TILE + vLane;

        // ---- S = Q @ K^T (3-term split, fp32 accum) ----
        float sacc[8][4];
        #pragma unroll
        for (int nt = 0; nt < 8; nt++)
            #pragma unroll
            for (int q = 0; q < 4; q++) sacc[nt][q] = 0.f;

        #pragma unroll
        for (int ks = 0; ks < 4; ks++) {
            const uint32_t ko = (uint32_t)(ks * 32);
            uint32_t qhf[4], qlf[4];
            ldm_x4(qhf, aQ + ko);
            ldm_x4(qlf, aQ + (uint32_t)AT_QL + ko);
            #pragma unroll
            for (int nb = 0; nb < 4; nb++) {
                uint32_t t[4], tl[4];
                ldm_x4(t,  bK + (uint32_t)(nb * 16 * AT_RS) + ko);
                ldm_x4(tl, bK + (uint32_t)(AT_TILE + nb * 16 * AT_RS) + ko);
                mma_bf16(sacc[2*nb],   qhf, t[0],  t[1]);
                mma_bf16(sacc[2*nb+1], qhf, t[2],  t[3]);
                mma_bf16(sacc[2*nb],   qhf, tl[0], tl[1]);
                mma_bf16(sacc[2*nb+1], qhf, tl[2], tl[3]);
                mma_bf16(sacc[2*nb],   qlf, t[0],  t[1]);
                mma_bf16(sacc[2*nb+1], qlf, t[2],  t[3]);
            }
        }

        // scale 1/sqrt(hd) = 0.125 (exact power of two)
        #pragma unroll
        for (int nt = 0; nt < 8; nt++) {
            sacc[nt][0] *= 0.125f; sacc[nt][1] *= 0.125f;
            sacc[nt][2] *= 0.125f; sacc[nt][3] *= 0.125f;
        }

        // ---- causal mask (diag block only) ----
        if (j == iq) {
            #pragma unroll
            for (int nt = 0; nt < 8; nt++) {
                const int col = j * 64 + nt * 8 + s * 2;
                if (col     > qrow0)     sacc[nt][0] = -1e30f;
                if (col + 1 > qrow0)     sacc[nt][1] = -1e30f;
                if (col     > qrow0 + 8) sacc[nt][2] = -1e30f;
                if (col + 1 > qrow0 + 8) sacc[nt][3] = -1e30f;
            }
        }

        // ---- online softmax on fragments ----
        float mx0 = -1e30f, mx1 = -1e30f;
        #pragma unroll
        for (int nt = 0; nt < 8; nt++) {
            mx0 = fmaxf(mx0, fmaxf(sacc[nt][0], sacc[nt][1]));
            mx1 = fmaxf(mx1, fmaxf(sacc[nt][2], sacc[nt][3]));
        }
        mx0 = fmaxf(mx0, __shfl_xor_sync(0xffffffffu, mx0, 1));
        mx0 = fmaxf(mx0, __shfl_xor_sync(0xffffffffu, mx0, 2));
        mx1 = fmaxf(mx1, __shfl_xor_sync(0xffffffffu, mx1, 1));
        mx1 = fmaxf(mx1, __shfl_xor_sync(0xffffffffu, mx1, 2));

        const float mn0 = fmaxf(m0v, mx0);
        const float mn1 = fmaxf(m1v, mx1);
        const float cr0 = __expf(m0v - mn0);
        const float cr1 = __expf(m1v - mn1);

        float rs0 = 0.f, rs1 = 0.f;
        #pragma unroll
        for (int nt = 0; nt < 8; nt++) {
            float p0 = __expf(sacc[nt][0] - mn0);
            float p1 = __expf(sacc[nt][1] - mn0);
            float p2 = __expf(sacc[nt][2] - mn1);
            float p3 = __expf(sacc[nt][3] - mn1);
            sacc[nt][0] = p0; sacc[nt][1] = p1;
            sacc[nt][2] = p2; sacc[nt][3] = p3;
            rs0 += p0 + p1;
            rs1 += p2 + p3;
        }
        rs0 += __shfl_xor_sync(0xffffffffu, rs0, 1);
        rs0 += __shfl_xor_sync(0xffffffffu, rs0, 2);
        rs1 += __shfl_xor_sync(0xffffffffu, rs1, 1);
        rs1 += __shfl_xor_sync(0xffffffffu, rs1, 2);

        l0v = l0v * cr0 + rs0;
        l1v = l1v * cr1 + rs1;
        m0v = mn0;
        m1v = mn1;
        #pragma unroll
        for (int nt = 0; nt < 8; nt++) {
            o[nt][0] *= cr0; o[nt][1] *= cr0;
            o[nt][2] *= cr1; o[nt][3] *= cr1;
        }

        // ---- O += P @ V (3-term; P from registers, V via ldmatrix.trans) ----
        #pragma unroll
        for (int ks = 0; ks < 4; ks++) {
            uint32_t ph[4], pl[4];
            ph[0] = packbf(sacc[2*ks][0],   sacc[2*ks][1]);
            ph[1] = packbf(sacc[2*ks][2],   sacc[2*ks][3]);
            ph[2] = packbf(sacc[2*ks+1][0], sacc[2*ks+1][1]);
            ph[3] = packbf(sacc[2*ks+1][2], sacc[2*ks+1][3]);
            pl[0] = lo_pack(ph[0], sacc[2*ks][0],   sacc[2*ks][1]);
            pl[1] = lo_pack(ph[1], sacc[2*ks][2],   sacc[2*ks][3]);
            pl[2] = lo_pack(ph[2], sacc[2*ks+1][0], sacc[2*ks+1][1]);
            pl[3] = lo_pack(ph[3], sacc[2*ks+1][2], sacc[2*ks+1][3]);

            const uint32_t krow = (uint32_t)(ks * 16 * AT_RS);
            #pragma unroll
            for (int nb = 0; nb < 4; nb++) {
                uint32_t t[4], tl[4];
                ldm_x4_t(t,  bV + krow + (uint32_t)(nb * 32));
                ldm_x4_t(tl, bV + (uint32_t)AT_TILE + krow + (uint32_t)(nb * 32));
                mma_bf16(o[2*nb],   ph, t[0],  t[1]);
                mma_bf16(o[2*nb+1], ph, t[2],  t[3]);
                mma_bf16(o[2*nb],   ph, tl[0], tl[1]);
                mma_bf16(o[2*nb+1], ph, tl[2], tl[3]);
                mma_bf16(o[2*nb],   pl, t[0],  t[1]);
                mma_bf16(o[2*nb+1], pl, t[2],  t[3]);
            }
        }
    }

    // ---- epilogue: normalize and write attn as hi/lo bf16 [B*T, D/2 u32] ----
    const float inv0 = 1.f / l0v;
    const float inv1 = 1.f / l1v;
    const size_t r0 = (size_t)b * TT + iq * 64 + w * 16 + g;
    #pragma unroll
    for (int nt = 0; nt < 8; nt++) {
        const int colw = h * 32 + nt * 4 + s;   // u32 column
        float v0 = o[nt][0] * inv0, v1 = o[nt][1] * inv0;
        float v2 = o[nt][2] * inv1, v3 = o[nt][3] * inv1;
        uint32_t h0 = packbf(v0, v1);
        uint32_t h1 = packbf(v2, v3);
        ah[r0 * DW + colw]       = h0;
        al[r0 * DW + colw]       = lo_pack(h0, v0, v1);
        ah[(r0 + 8) * DW + colw] = h1;
        al[(r0 + 8) * DW + colw] = lo_pack(h1, v2, v3);
    }
}

// ===========================================================================
// Launch: splits -> qkv GEMM (split-out) -> flash (split-out) -> out GEMM.
// ===========================================================================
extern "C" void kernel_launch(void* const* d_in, const int* in_sizes, int n_in,
                              void* d_out, int out_size)
{
    const float* x    = (const float*)d_in[0];
    const float* Wqkv = (const float*)d_in[1];
    const float* bqkv = (const float*)d_in[2];
    const float* Wout = (const float*)d_in[3];
    const float* bout = (const float*)d_in[4];
    float*       out  = (float*)d_out;

    uint32_t *xh, *xl, *wqh, *wql, *woh, *wol, *qhp, *qlp, *ahp, *alp;
    cudaGetSymbolAddress((void**)&xh,  g_xh);
    cudaGetSymbolAddress((void**)&xl,  g_xl);
    cudaGetSymbolAddress((void**)&wqh, g_wqh);
    cudaGetSymbolAddress((void**)&wql, g_wql);
    cudaGetSymbolAddress((void**)&woh, g_woh);
    cudaGetSymbolAddress((void**)&wol, g_wol);
    cudaGetSymbolAddress((void**)&qhp, g_qh);
    cudaGetSymbolAddress((void**)&qlp, g_ql);
    cudaGetSymbolAddress((void**)&ahp, g_ah);
    cudaGetSymbolAddress((void**)&alp, g_al);

    cudaFuncSetAttribute(bf16x3_gemm_async,
                         cudaFuncAttributeMaxDynamicSharedMemorySize, GK_SMEM);
    cudaFuncSetAttribute(flash_attn_mma,
                         cudaFuncAttributeMaxDynamicSharedMemorySize, AT_SMEM);

    // 0) pre-split fp32 -> bf16 hi/lo
    {
        int n4;
        n4 = MROWS * DD / 4;
        split_f32<<<(n4 + 255) / 256, 256>>>((const float4*)x, (uint2*)xh, (uint2*)xl, n4);
        n4 = NQKV * DD / 4;
        split_f32<<<(n4 + 255) / 256, 256>>>((const float4*)Wqkv, (uint2*)wqh, (uint2*)wql, n4);
        n4 = DD * DD / 4;
        split_f32<<<(n4 + 255) / 256, 256>>>((const float4*)Wout, (uint2*)woh, (uint2*)wol, n4);
    }
    // 1) qkv = x @ Wqkv^T + bqkv -> hi/lo bf16
    {
        dim3 grid(NQKV / 128, MROWS / 128);   // (24, 32)
        bf16x3_gemm_async<<<grid, 256, GK_SMEM>>>(xh, xl, wqh, wql, bqkv,
                                                  nullptr, qhp, qlp,
                                                  MROWS, NQKV, DD, 1);
    }
    // 2) attention -> hi/lo bf16
    {
        dim3 grid(TT / 64, HH, BB);           // (32, 16, 2)
        flash_attn_mma<<<grid, 128, AT_SMEM>>>(qhp, qlp, ahp, alp);
    }
    // 3) out = attn @ Wout^T + bout (fp32)
    {
        dim3 grid(DD / 128, MROWS / 128);     // (8, 32)
        bf16x3_gemm_async<<<grid, 256, GK_SMEM>>>(ahp, alp, woh, wol, bout,
                                                  out, nullptr, nullptr,
                                                  MROWS, DD, DD, 0);
    }
}